// round 6
// baseline (speedup 1.0000x reference)
#include <cuda_runtime.h>
#include <cuda_fp16.h>
#include <cstdint>
#include <cstddef>

// ============================================================================
// Mex forward: y[n,i] = log( sum_k exp(P[n,k]) * exp(O[i,k]) ) - ln(576)
// pass1: im2col+exp -> fp16 A (known good)
// pass0: exp(offsets) -> fp16 B (known good)
// gemm : 256-thread mma.sync GEMM, CTA tile M=128 x N=256, warp tile 64x64
//        (LDSM:HMMA = 1:8), K=576 as 9x64, double-buffered cp.async,
//        smem-transposed log epilogue with coalesced float4 stores.
// ============================================================================

#define DINL __device__ __forceinline__

static constexpr int CC   = 64;
static constexpr int HH   = 64;
static constexpr int WW   = 64;
static constexpr int NI   = 256;
static constexpr int KTOT = 576;
static constexpr int NPIX = 65536;
static constexpr int MTILE  = 128;
static constexpr int KCHUNK = 64;
static constexpr int NCHUNK = 9;
static constexpr float LOG_K = 6.3561076606958915f;  // ln(576)

__device__ __half g_A[(size_t)NPIX * KTOT];   // ~75.5 MB scratch
__device__ __half g_B[(size_t)NI * KTOT];     // 288 KB

// ---------------------------------------------------------------------------
DINL uint32_t smem_u32(const void* p) {
    uint32_t a;
    asm("{ .reg .u64 t; cvta.to.shared.u64 t, %1; cvt.u32.u64 %0, t; }"
        : "=r"(a) : "l"(p));
    return a;
}
DINL void cp_async16(uint32_t smem_addr, const void* gptr) {
    asm volatile("cp.async.cg.shared.global [%0], [%1], 16;"
                 :: "r"(smem_addr), "l"(gptr) : "memory");
}
DINL void cp_commit() { asm volatile("cp.async.commit_group;" ::: "memory"); }
template <int N> DINL void cp_wait() {
    asm volatile("cp.async.wait_group %0;" :: "n"(N) : "memory");
}
DINL void ldm_x4(uint32_t addr, uint32_t& r0, uint32_t& r1,
                 uint32_t& r2, uint32_t& r3) {
    asm volatile("ldmatrix.sync.aligned.m8n8.x4.shared.b16 {%0,%1,%2,%3}, [%4];"
                 : "=r"(r0), "=r"(r1), "=r"(r2), "=r"(r3) : "r"(addr));
}
DINL void mma16816(float* c, const uint32_t* a, uint32_t b0, uint32_t b1) {
    asm volatile(
        "mma.sync.aligned.m16n8k16.row.col.f32.f16.f16.f32 "
        "{%0,%1,%2,%3}, {%4,%5,%6,%7}, {%8,%9}, {%0,%1,%2,%3};"
        : "+f"(c[0]), "+f"(c[1]), "+f"(c[2]), "+f"(c[3])
        : "r"(a[0]), "r"(a[1]), "r"(a[2]), "r"(a[3]), "r"(b0), "r"(b1));
}
DINL uint32_t sw128(uint32_t off) { return off ^ ((off >> 3) & 0x70); }

// ---------------------------------------------------------------------------
// pass0: B[i,k] = fp16(exp(offsets[i,k]))   (known good)
// ---------------------------------------------------------------------------
__global__ void mex_pass0(const float* __restrict__ offs, __half* __restrict__ Bm) {
    int i = blockIdx.x * blockDim.x + threadIdx.x;
    if (i < NI * KTOT) Bm[i] = __float2half_rn(__expf(offs[i]));
}

// ---------------------------------------------------------------------------
// pass1: im2col + exp.  One CTA per (b, oh).   (known good)
// ---------------------------------------------------------------------------
__global__ void __launch_bounds__(256) mex_pass1(const float* __restrict__ x,
                                                 __half* __restrict__ A) {
    __shared__ __half xs[CC * 3 * 66];
    const int bo  = blockIdx.x;
    const int b   = bo >> 5;
    const int oh  = bo & 31;
    const int tid = threadIdx.x;
    const float* xb = x + (size_t)b * (CC * HH * WW);

    for (int idx = tid; idx < CC * 3 * 66; idx += 256) {
        int c  = idx / 198;
        int rr = idx - c * 198;
        int fh = rr / 66;
        int w  = rr - fh * 66 - 1;
        int ih = oh * 2 - 1 + fh;
        bool ok = (ih >= 0) & (ih < HH) & (w >= 0) & (w < WW);
        float v = ok ? xb[((c << 6) + ih) * 64 + w] : 0.0f;
        xs[idx] = __float2half_rn(ok ? __expf(v) : 1.0f);
    }
    __syncthreads();

    __half* Ab = A + (size_t)bo * (32 * KTOT);
#pragma unroll
    for (int it = 0; it < 9; it++) {
        int l  = (it * 256 + tid) * 8;
        int ow = l / KTOT;
        int k0 = l - ow * KTOT;
        __align__(16) __half tmp[8];
#pragma unroll
        for (int j = 0; j < 8; j++) {
            int k  = k0 + j;
            int c  = k / 9;
            int r9 = k - c * 9;
            int fh = r9 / 3;
            int fw = r9 - fh * 3;
            tmp[j] = xs[(c * 3 + fh) * 66 + ow * 2 + fw];
        }
        *reinterpret_cast<uint4*>(Ab + l) = *reinterpret_cast<const uint4*>(tmp);
    }
}

// ---------------------------------------------------------------------------
// gemm: 256 threads, 8 warps (wm = wid&1 -> M 64-band, wn = wid>>1 -> N 64-band)
// ---------------------------------------------------------------------------
static constexpr int A_STAGE = 128 * 128;      // 16 KB
static constexpr int B_STAGE = 256 * 128;      // 32 KB
static constexpr int A0_OFF = 0;
static constexpr int B0_OFF = 2 * A_STAGE;     // 32768
static constexpr int SMEM_BYTES = 2 * A_STAGE + 2 * B_STAGE + 128;  // 98432

DINL void load_chunk(uint32_t a_s, uint32_t b_s, int tid,
                     const __half* Abase, const __half* Bg, int kc) {
    const __half* ap = Abase + kc * KCHUNK;
    const __half* bp = Bg + kc * KCHUNK;
#pragma unroll
    for (int i = 0; i < 4; i++) {            // A: 128 rows x 8 x 16B
        int idx = tid + i * 256;
        int row = idx >> 3, ch = idx & 7;
        uint32_t off = (uint32_t)(row * 128 + ch * 16);
        cp_async16(a_s + sw128(off), ap + (size_t)row * KTOT + ch * 8);
    }
#pragma unroll
    for (int i = 0; i < 8; i++) {            // B: 256 rows x 8 x 16B
        int idx = tid + i * 256;
        int row = idx >> 3, ch = idx & 7;
        uint32_t off = (uint32_t)(row * 128 + ch * 16);
        cp_async16(b_s + sw128(off), bp + (size_t)row * KTOT + ch * 8);
    }
    cp_commit();
}

__global__ void __launch_bounds__(256, 1) mex_gemm(const __half* __restrict__ Ag,
                                                   const __half* __restrict__ Bg,
                                                   float* __restrict__ out) {
    extern __shared__ __align__(128) char sm[];
    const uint32_t sb = smem_u32(sm);

    const int tid = threadIdx.x;
    const int l   = tid & 31;
    const int wid = tid >> 5;
    const int wm  = wid & 1;        // M band: wm*64
    const int wn  = wid >> 1;       // N band: wn*64

    const int m0 = blockIdx.x * MTILE;
    const __half* Abase = Ag + (size_t)m0 * KTOT;

    float acc[4][8][4];
#pragma unroll
    for (int a = 0; a < 4; a++)
#pragma unroll
        for (int n = 0; n < 8; n++)
#pragma unroll
            for (int e = 0; e < 4; e++) acc[a][n][e] = 0.0f;

    const uint32_t lrow = (uint32_t)(l & 15);
    const uint32_t lcol = (uint32_t)((l >> 4) * 16);

    load_chunk(sb + A0_OFF, sb + B0_OFF, tid, Abase, Bg, 0);

    for (int kc = 0; kc < NCHUNK; kc++) {
        const int s = kc & 1;
        if (kc + 1 < NCHUNK) {
            load_chunk(sb + A0_OFF + (s ^ 1) * A_STAGE,
                       sb + B0_OFF + (s ^ 1) * B_STAGE, tid, Abase, Bg, kc + 1);
            cp_wait<1>();
        } else {
            cp_wait<0>();
        }
        __syncthreads();

        const uint32_t a_s = sb + A0_OFF + s * A_STAGE;
        const uint32_t b_s = sb + B0_OFF + s * B_STAGE;
#pragma unroll
        for (int ks = 0; ks < 4; ks++) {
            uint32_t af[4][4], bf[4][4];
#pragma unroll
            for (int mt = 0; mt < 4; mt++) {
                uint32_t off = (uint32_t)((wm * 64 + mt * 16 + lrow) * 128 +
                                          ks * 32 + lcol);
                ldm_x4(a_s + sw128(off), af[mt][0], af[mt][1], af[mt][2], af[mt][3]);
            }
#pragma unroll
            for (int bt = 0; bt < 4; bt++) {
                uint32_t off = (uint32_t)((wn * 64 + bt * 16 + lrow) * 128 +
                                          ks * 32 + lcol);
                ldm_x4(b_s + sw128(off), bf[bt][0], bf[bt][1], bf[bt][2], bf[bt][3]);
            }
#pragma unroll
            for (int mt = 0; mt < 4; mt++)
#pragma unroll
                for (int nt = 0; nt < 8; nt++)
                    mma16816(acc[mt][nt], af[mt],
                             bf[nt >> 1][nt & 1], bf[nt >> 1][(nt & 1) + 2]);
        }
        __syncthreads();   // stage s free before next iter's cp.async overwrites it
    }

    // ---- epilogue: 4 groups of 64 instances; smem transpose -> coalesced ----
    float* fs = reinterpret_cast<float*>(sm);    // [128][65] floats = 33280 B
    const int bglob = m0 >> 10;
    const int mrem  = m0 & 1023;
#pragma unroll 1
    for (int g = 0; g < 4; g++) {
        __syncthreads();
        if (wn == g) {
#pragma unroll
            for (int mt = 0; mt < 4; mt++)
#pragma unroll
                for (int nt = 0; nt < 8; nt++)
#pragma unroll
                    for (int e = 0; e < 4; e++) {
                        int row = (l >> 2) + ((e >> 1) << 3);
                        int col = ((l & 3) << 1) + (e & 1);
                        int ml  = wm * 64 + mt * 16 + row;
                        int nl  = (nt << 3) + col;
                        fs[ml * 65 + nl] = __logf(acc[mt][nt][e]) - LOG_K;
                    }
        }
        __syncthreads();
        const int i_lo = tid >> 3;               // 0..31
        const int mc   = (tid & 7) << 4;         // 0..112
#pragma unroll
        for (int h = 0; h < 2; h++) {
            const int i_loc = i_lo + h * 32;     // 0..63
            float* ob = out + ((size_t)bglob << 18)
                            + (((size_t)(g * 64 + i_loc)) << 10) + mrem + mc;
#pragma unroll
            for (int j = 0; j < 4; j++) {
                float4 v;
                v.x = fs[(mc + j * 4 + 0) * 65 + i_loc];
                v.y = fs[(mc + j * 4 + 1) * 65 + i_loc];
                v.z = fs[(mc + j * 4 + 2) * 65 + i_loc];
                v.w = fs[(mc + j * 4 + 3) * 65 + i_loc];
                *reinterpret_cast<float4*>(ob + j * 4) = v;
            }
        }
    }
}

// ---------------------------------------------------------------------------
extern "C" void kernel_launch(void* const* d_in, const int* in_sizes, int n_in,
                              void* d_out, int out_size) {
    const float* x    = (const float*)d_in[0];
    const float* offs = (const float*)d_in[1];
    if (n_in >= 2 && in_sizes[0] == NI * KTOT) {  // defensive: swap if order flipped
        const float* t = x; x = offs; offs = t;
    }
    float* out = (float*)d_out;

    __half *Ap = nullptr, *Bp = nullptr;
    cudaGetSymbolAddress((void**)&Ap, g_A);
    cudaGetSymbolAddress((void**)&Bp, g_B);
    cudaFuncSetAttribute(mex_gemm, cudaFuncAttributeMaxDynamicSharedMemorySize,
                         SMEM_BYTES);

    // order chosen so ncu (-s 5 -c 1) lands on mex_gemm of the 2nd invocation
    mex_pass1<<<64 * 32, 256>>>(x, Ap);
    mex_pass0<<<(NI * KTOT + 255) / 256, 256>>>(offs, Bp);
    mex_gemm<<<NPIX / MTILE, 256, SMEM_BYTES>>>(Ap, Bp, out);
}

// round 7
// speedup vs baseline: 1.2144x; 1.2144x over previous
#include <cuda_runtime.h>
#include <cuda_fp16.h>
#include <cstdint>
#include <cstddef>

// ============================================================================
// Mex forward: y[n,i] = log( sum_k exp(P[n,k]) * exp(O[i,k]) ) - ln(576)
// K axis permuted: k' = (fh*3+fw)*64 + c  (applied to BOTH A and B, so the
// GEMM result is identical). This makes the im2col build a constant-stride
// smem gather (no per-element div/mod) -- pass1 was ALU-bound at 63us.
// pass1: im2col+exp -> fp16 A (permuted-K, cheap build)
// pass0: exp(offsets) -> fp16 B (permuted-K)
// gemm : R3-verbatim mma.sync GEMM (128x128 tile, 2 CTA/SM, warp 64x32)
// ============================================================================

#define DINL __device__ __forceinline__

static constexpr int CC   = 64;
static constexpr int HH   = 64;
static constexpr int WW   = 64;
static constexpr int NI   = 256;
static constexpr int KTOT = 576;
static constexpr int NPIX = 65536;
static constexpr int MTILE  = 128;
static constexpr int NTILE  = 128;
static constexpr int KCHUNK = 64;
static constexpr int NCHUNK = 9;
static constexpr float LOG_K = 6.3561076606958915f;  // ln(576)

__device__ __half g_A[(size_t)NPIX * KTOT];   // ~75.5 MB scratch
__device__ __half g_B[(size_t)NI * KTOT];     // 288 KB

// ---------------------------------------------------------------------------
DINL uint32_t smem_u32(const void* p) {
    uint32_t a;
    asm("{ .reg .u64 t; cvta.to.shared.u64 t, %1; cvt.u32.u64 %0, t; }"
        : "=r"(a) : "l"(p));
    return a;
}
DINL void cp_async16(uint32_t smem_addr, const void* gptr) {
    asm volatile("cp.async.cg.shared.global [%0], [%1], 16;"
                 :: "r"(smem_addr), "l"(gptr) : "memory");
}
DINL void cp_commit() { asm volatile("cp.async.commit_group;" ::: "memory"); }
template <int N> DINL void cp_wait() {
    asm volatile("cp.async.wait_group %0;" :: "n"(N) : "memory");
}
DINL void ldm_x4(uint32_t addr, uint32_t& r0, uint32_t& r1,
                 uint32_t& r2, uint32_t& r3) {
    asm volatile("ldmatrix.sync.aligned.m8n8.x4.shared.b16 {%0,%1,%2,%3}, [%4];"
                 : "=r"(r0), "=r"(r1), "=r"(r2), "=r"(r3) : "r"(addr));
}
DINL void mma16816(float* c, const uint32_t* a, uint32_t b0, uint32_t b1) {
    asm volatile(
        "mma.sync.aligned.m16n8k16.row.col.f32.f16.f16.f32 "
        "{%0,%1,%2,%3}, {%4,%5,%6,%7}, {%8,%9}, {%0,%1,%2,%3};"
        : "+f"(c[0]), "+f"(c[1]), "+f"(c[2]), "+f"(c[3])
        : "r"(a[0]), "r"(a[1]), "r"(a[2]), "r"(a[3]), "r"(b0), "r"(b1));
}
DINL uint32_t sw128(uint32_t off) { return off ^ ((off >> 3) & 0x70); }

// ---------------------------------------------------------------------------
// pass0: B'[i, f*64+c] = fp16(exp(offsets[i, c*9+f]))
// ---------------------------------------------------------------------------
__global__ void mex_pass0(const float* __restrict__ offs, __half* __restrict__ Bm) {
    int j = blockIdx.x * blockDim.x + threadIdx.x;
    if (j < NI * KTOT) {
        int i = j / KTOT;
        int r = j - i * KTOT;
        int f = r >> 6;
        int c = r & 63;
        Bm[j] = __float2half_rn(__expf(offs[i * KTOT + c * 9 + f]));
    }
}

// ---------------------------------------------------------------------------
// pass1: im2col + exp, permuted K.  One CTA per (b, oh).
// A'[n, f*64+c] = exp(x[b, c, 2oh-1+fh, 2ow-1+fw]),  f = fh*3+fw
// slab layout (same as known-good R3): xs[c][fh][w+1], pitch 66
// ---------------------------------------------------------------------------
__global__ void __launch_bounds__(256) mex_pass1(const float* __restrict__ x,
                                                 __half* __restrict__ A) {
    __shared__ __half xs[CC * 3 * 66];      // 12672 halves
    const int bo  = blockIdx.x;             // b*32 + oh
    const int b   = bo >> 5;
    const int oh  = bo & 31;
    const int tid = threadIdx.x;
    const float* xb = x + (size_t)b * (CC * HH * WW);

    // fill: half2 units over (c, fh, w-pair).  6336 units = 64*3*33
#pragma unroll
    for (int it = 0; it < 25; it++) {
        int u = tid + it * 256;
        if (u < 6336) {
            int c  = u / 99;
            int rr = u - 99 * c;
            int fh = rr / 33;
            int wp = rr - 33 * fh;
            int w0 = 2 * wp - 1;             // -1 .. 63 (w0+1: 0..64)
            int ih = oh * 2 - 1 + fh;
            __half2 hv;
            if (ih >= 0) {                   // ih <= 63 always
                const float* row = xb + ((c << 6) + ih) * 64;
                float v0 = (w0 >= 0) ? __expf(row[w0]) : 1.0f;
                float v1 = (w0 + 1 <= 63) ? __expf(row[w0 + 1]) : 1.0f;
                hv = __floats2half2_rn(v0, v1);
            } else {
                hv = __halves2half2(__ushort_as_half(0x3C00), __ushort_as_half(0x3C00));
            }
            *reinterpret_cast<__half2*>(&xs[(c * 3 + fh) * 66 + 2 * wp]) = hv;
        }
    }
    __syncthreads();

    // build: 2304 16B-stores; each = 8 consecutive c at fixed (ow, f)
    __half* Ab = A + (size_t)bo * (32 * KTOT);
#pragma unroll
    for (int it = 0; it < 9; it++) {
        int idx = it * 256 + tid;            // 0..2303
        int ow  = idx / 72;
        int rem = idx - ow * 72;
        int f   = rem >> 3;                  // 0..8
        int c0  = (rem & 7) << 3;            // 0..56
        int fh  = (f * 11) >> 5;             // f/3
        int fw  = f - 3 * fh;
        const __half* src = &xs[(c0 * 3 + fh) * 66 + 2 * ow + fw];
        __align__(16) __half tmp[8];
#pragma unroll
        for (int j = 0; j < 8; j++) tmp[j] = src[j * 198];
        *reinterpret_cast<uint4*>(Ab + (size_t)idx * 8) =
            *reinterpret_cast<const uint4*>(tmp);
    }
}

// ---------------------------------------------------------------------------
// gemm (R3 verbatim): CTA tile 128x128, 8 warps (2M x 4N), warp 64x32,
// K-chunk 64, SW128-swizzled smem, double-buffered cp.async.
// grid = (2, 512): x = N-split, y = M tile.
// ---------------------------------------------------------------------------
static constexpr int STAGE_BYTES = 128 * 128;
static constexpr int A0_OFF = 0;
static constexpr int A1_OFF = STAGE_BYTES;
static constexpr int B0_OFF = 2 * STAGE_BYTES;
static constexpr int B1_OFF = 3 * STAGE_BYTES;
static constexpr int SMEM_BYTES = 4 * STAGE_BYTES + 128;

DINL void load_chunk(uint32_t a_s, uint32_t b_s, int tid,
                     const __half* Abase, const __half* Bbase, int kc) {
    const __half* ap = Abase + kc * KCHUNK;
    const __half* bp = Bbase + kc * KCHUNK;
#pragma unroll
    for (int i = 0; i < 4; i++) {
        int idx = tid + i * 256;
        int row = idx >> 3, ch = idx & 7;
        uint32_t off = (uint32_t)(row * 128 + ch * 16);
        cp_async16(a_s + sw128(off), ap + (size_t)row * KTOT + ch * 8);
    }
#pragma unroll
    for (int i = 0; i < 4; i++) {
        int idx = tid + i * 256;
        int row = idx >> 3, ch = idx & 7;
        uint32_t off = (uint32_t)(row * 128 + ch * 16);
        cp_async16(b_s + sw128(off), bp + (size_t)row * KTOT + ch * 8);
    }
}

__global__ void __launch_bounds__(256, 2) mex_gemm(const __half* __restrict__ Ag,
                                                   const __half* __restrict__ Bg,
                                                   float* __restrict__ out) {
    extern __shared__ __align__(128) char smem_raw[];
    char* smem_al = (char*)(((uintptr_t)smem_raw + 127) & ~(uintptr_t)127);
    const uint32_t sb = smem_u32(smem_al);

    const int tid = threadIdx.x;
    const int l   = tid & 31;
    const int wid = tid >> 5;
    const int wm  = wid >> 2;       // 0..1 -> M offset wm*64
    const int wn  = wid & 3;        // 0..3 -> N offset wn*32

    const int n0 = blockIdx.x * NTILE;     // 0 or 128
    const int m0 = blockIdx.y * MTILE;
    const __half* Abase = Ag + (size_t)m0 * KTOT;
    const __half* Bbase = Bg + (size_t)n0 * KTOT;

    float acc[4][4][4];
#pragma unroll
    for (int a = 0; a < 4; a++)
#pragma unroll
        for (int b = 0; b < 4; b++)
#pragma unroll
            for (int e = 0; e < 4; e++) acc[a][b][e] = 0.0f;

    const uint32_t lrow = (uint32_t)(l & 15);
    const uint32_t lcol = (uint32_t)((l >> 4) * 16);

    load_chunk(sb + A0_OFF, sb + B0_OFF, tid, Abase, Bbase, 0);
    cp_commit();

    for (int kc = 0; kc < NCHUNK; kc++) {
        const int s = kc & 1;
        if (kc + 1 < NCHUNK) {
            load_chunk(sb + (s ? A0_OFF : A1_OFF), sb + (s ? B0_OFF : B1_OFF),
                       tid, Abase, Bbase, kc + 1);
            cp_commit();
            cp_wait<1>();
        } else {
            cp_wait<0>();
        }
        __syncthreads();

        const uint32_t a_s = sb + (s ? A1_OFF : A0_OFF);
        const uint32_t b_s = sb + (s ? B1_OFF : B0_OFF);
#pragma unroll
        for (int ks = 0; ks < 4; ks++) {
            uint32_t af[4][4], bf[2][4];
#pragma unroll
            for (int mt = 0; mt < 4; mt++) {
                uint32_t off = (uint32_t)((wm * 64 + mt * 16 + lrow) * 128 +
                                          ks * 32 + lcol);
                ldm_x4(a_s + sw128(off), af[mt][0], af[mt][1], af[mt][2], af[mt][3]);
            }
#pragma unroll
            for (int bt = 0; bt < 2; bt++) {
                uint32_t off = (uint32_t)((wn * 32 + bt * 16 + lrow) * 128 +
                                          ks * 32 + lcol);
                ldm_x4(b_s + sw128(off), bf[bt][0], bf[bt][1], bf[bt][2], bf[bt][3]);
            }
#pragma unroll
            for (int mt = 0; mt < 4; mt++)
#pragma unroll
                for (int nt = 0; nt < 4; nt++)
                    mma16816(acc[mt][nt], af[mt],
                             bf[nt >> 1][nt & 1], bf[nt >> 1][(nt & 1) + 2]);
        }
        __syncthreads();
    }

    // ---- epilogue: per 32-instance group, smem transpose -> log -> coalesced
    float* fs = (float*)smem_al;                 // 128 x 33 floats
    const int bglob = m0 >> 10;
    const int mrem  = m0 & 1023;
#pragma unroll 1
    for (int g = 0; g < 4; g++) {
        __syncthreads();
        if (wn == g) {
#pragma unroll
            for (int mt = 0; mt < 4; mt++)
#pragma unroll
                for (int nt = 0; nt < 4; nt++)
#pragma unroll
                    for (int e = 0; e < 4; e++) {
                        int row = (l >> 2) + (e >> 1) * 8;
                        int col = (l & 3) * 2 + (e & 1);
                        int ml = wm * 64 + mt * 16 + row;
                        int nl = nt * 8 + col;
                        fs[ml * 33 + nl] = __logf(acc[mt][nt][e]) - LOG_K;
                    }
        }
        __syncthreads();
        const int i_loc = tid >> 3;              // 0..31
        const int mc    = (tid & 7) * 16;        // 0..112
        const int i_glb = n0 + g * 32 + i_loc;
        float* ob = out + ((size_t)bglob << 18) + ((size_t)i_glb << 10) + mrem + mc;
#pragma unroll
        for (int j = 0; j < 4; j++) {
            float4 v;
            v.x = fs[(mc + j * 4 + 0) * 33 + i_loc];
            v.y = fs[(mc + j * 4 + 1) * 33 + i_loc];
            v.z = fs[(mc + j * 4 + 2) * 33 + i_loc];
            v.w = fs[(mc + j * 4 + 3) * 33 + i_loc];
            *reinterpret_cast<float4*>(ob + j * 4) = v;
        }
    }
}

// ---------------------------------------------------------------------------
extern "C" void kernel_launch(void* const* d_in, const int* in_sizes, int n_in,
                              void* d_out, int out_size) {
    const float* x    = (const float*)d_in[0];
    const float* offs = (const float*)d_in[1];
    if (n_in >= 2 && in_sizes[0] == NI * KTOT) {  // defensive: swap if order flipped
        const float* t = x; x = offs; offs = t;
    }
    float* out = (float*)d_out;

    __half *Ap = nullptr, *Bp = nullptr;
    cudaGetSymbolAddress((void**)&Ap, g_A);
    cudaGetSymbolAddress((void**)&Bp, g_B);
    cudaFuncSetAttribute(mex_gemm, cudaFuncAttributeMaxDynamicSharedMemorySize,
                         SMEM_BYTES);

    // pass1 first so ncu (-s 5 -c 1) profiles the NEW pass1
    mex_pass1<<<64 * 32, 256>>>(x, Ap);
    mex_pass0<<<(NI * KTOT + 255) / 256, 256>>>(offs, Bp);
    dim3 grid(2, NPIX / MTILE);
    mex_gemm<<<grid, 256, SMEM_BYTES>>>(Ap, Bp, out);
}

// round 8
// speedup vs baseline: 1.5124x; 1.2454x over previous
#include <cuda_runtime.h>
#include <cuda_fp16.h>
#include <cstdint>
#include <cstddef>

// ============================================================================
// Mex forward: y[n,i] = log( sum_k exp(P[n,k]) * exp(O[i,k]) ) - ln(576)
// K axis permuted: k' = (fh*3+fw)*64 + c (applied to both A and B).
// pass1 v3: slab stored c-fastest ([fh][iw+1][c], pitch 72) so the im2col
//   build is one LDS.128 per 16B of A; fill does the transpose in registers
//   (coalesced LDG down the c-stride, conflict-free STS.128).
// pass0 / gemm: R7 verbatim (proven).
// ============================================================================

#define DINL __device__ __forceinline__

static constexpr int CC   = 64;
static constexpr int HH   = 64;
static constexpr int WW   = 64;
static constexpr int NI   = 256;
static constexpr int KTOT = 576;
static constexpr int NPIX = 65536;
static constexpr int MTILE  = 128;
static constexpr int NTILE  = 128;
static constexpr int KCHUNK = 64;
static constexpr int NCHUNK = 9;
static constexpr float LOG_K = 6.3561076606958915f;  // ln(576)

static constexpr int SLAB_P = 72;                    // halves per (fh,iw') row
static constexpr int SLAB_BYTES = 3 * 65 * SLAB_P * 2;  // 56160 (> 48K: dynamic)

__device__ __half g_A[(size_t)NPIX * KTOT];   // ~75.5 MB scratch
__device__ __half g_B[(size_t)NI * KTOT];     // 288 KB

// ---------------------------------------------------------------------------
DINL uint32_t smem_u32(const void* p) {
    uint32_t a;
    asm("{ .reg .u64 t; cvta.to.shared.u64 t, %1; cvt.u32.u64 %0, t; }"
        : "=r"(a) : "l"(p));
    return a;
}
DINL void cp_async16(uint32_t smem_addr, const void* gptr) {
    asm volatile("cp.async.cg.shared.global [%0], [%1], 16;"
                 :: "r"(smem_addr), "l"(gptr) : "memory");
}
DINL void cp_commit() { asm volatile("cp.async.commit_group;" ::: "memory"); }
template <int N> DINL void cp_wait() {
    asm volatile("cp.async.wait_group %0;" :: "n"(N) : "memory");
}
DINL void ldm_x4(uint32_t addr, uint32_t& r0, uint32_t& r1,
                 uint32_t& r2, uint32_t& r3) {
    asm volatile("ldmatrix.sync.aligned.m8n8.x4.shared.b16 {%0,%1,%2,%3}, [%4];"
                 : "=r"(r0), "=r"(r1), "=r"(r2), "=r"(r3) : "r"(addr));
}
DINL void mma16816(float* c, const uint32_t* a, uint32_t b0, uint32_t b1) {
    asm volatile(
        "mma.sync.aligned.m16n8k16.row.col.f32.f16.f16.f32 "
        "{%0,%1,%2,%3}, {%4,%5,%6,%7}, {%8,%9}, {%0,%1,%2,%3};"
        : "+f"(c[0]), "+f"(c[1]), "+f"(c[2]), "+f"(c[3])
        : "r"(a[0]), "r"(a[1]), "r"(a[2]), "r"(a[3]), "r"(b0), "r"(b1));
}
DINL uint32_t sw128(uint32_t off) { return off ^ ((off >> 3) & 0x70); }

// ---------------------------------------------------------------------------
// pass0 (R7 verbatim): B'[i, f*64+c] = fp16(exp(offsets[i, c*9+f]))
// ---------------------------------------------------------------------------
__global__ void mex_pass0(const float* __restrict__ offs, __half* __restrict__ Bm) {
    int j = blockIdx.x * blockDim.x + threadIdx.x;
    if (j < NI * KTOT) {
        int i = j / KTOT;
        int r = j - i * KTOT;
        int f = r >> 6;
        int c = r & 63;
        Bm[j] = __float2half_rn(__expf(offs[i * KTOT + c * 9 + f]));
    }
}

// ---------------------------------------------------------------------------
// pass1 v3: one CTA per (b, oh).  Slab xs[fh][iw'][c], iw' = iw+1 in [0,64],
// pitch SLAB_P=72 halves; row iw'=0 holds exp(0)=1 (left pad).
// Fill: warp wid owns c-octet c0=8*wid; lane l covers w = 32h+l.
//   For each j<8: LDG x[c0+j, ih, w] (coalesced 128B across the warp), exp,
//   pack 8 c's into one uint4, STS.128 at (fh,w+1,c0) -- bank-stride 4, clean.
// Build: A'[n=ow, f*64+c0..c0+7] = one LDS.128 at (fh, 2ow+fw, c0); STG.128.
// ---------------------------------------------------------------------------
__global__ void __launch_bounds__(256) mex_pass1(const float* __restrict__ x,
                                                 __half* __restrict__ A) {
    extern __shared__ __align__(16) __half xs[];   // [3][65][72]
    const int bo  = blockIdx.x;             // b*32 + oh
    const int b   = bo >> 5;
    const int oh  = bo & 31;
    const int tid = threadIdx.x;
    const int l   = tid & 31;
    const int wid = tid >> 5;
    const float* xb = x + ((size_t)b << 18);

    // left-pad row iw'=0: ones (exp of zero padding)
    if (tid < 96) {
        int fh = tid >> 5;
        int c  = (tid & 31) << 1;
        *reinterpret_cast<__half2*>(&xs[(fh * 65) * SLAB_P + c]) =
            __halves2half2(__ushort_as_half(0x3C00), __ushort_as_half(0x3C00));
    }

    // fill (register transpose)
    const int c0 = wid << 3;
#pragma unroll
    for (int fh = 0; fh < 3; fh++) {
        const int ih = 2 * oh - 1 + fh;            // in [-1, 63]
#pragma unroll
        for (int h = 0; h < 2; h++) {
            const int w = (h << 5) + l;            // 0..63
            __align__(16) __half tmp[8];
            if (ih >= 0) {
                const float* p = xb + ((size_t)c0 << 12) + (ih << 6) + w;
#pragma unroll
                for (int j = 0; j < 8; j++)
                    tmp[j] = __float2half_rn(__expf(p[(size_t)j << 12]));
            } else {
#pragma unroll
                for (int j = 0; j < 8; j++) tmp[j] = __ushort_as_half(0x3C00);
            }
            *reinterpret_cast<uint4*>(&xs[(fh * 65 + w + 1) * SLAB_P + c0]) =
                *reinterpret_cast<const uint4*>(tmp);
        }
    }
    __syncthreads();

    // build: 2304 x (LDS.128 -> STG.128)
    __half* Ab = A + (size_t)bo * (32 * KTOT);
#pragma unroll
    for (int it = 0; it < 9; it++) {
        int idx = it * 256 + tid;            // 0..2303
        int ow  = idx / 72;
        int rem = idx - ow * 72;
        int f   = rem >> 3;                  // 0..8
        int cq  = rem & 7;
        int fh  = (f * 11) >> 5;             // f/3
        int fw  = f - 3 * fh;
        uint4 v = *reinterpret_cast<const uint4*>(
            &xs[(fh * 65 + 2 * ow + fw) * SLAB_P + (cq << 3)]);
        *reinterpret_cast<uint4*>(Ab + (size_t)idx * 8) = v;
    }
}

// ---------------------------------------------------------------------------
// gemm (R7 verbatim): CTA tile 128x128, 8 warps (2M x 4N), warp 64x32,
// K-chunk 64, SW128-swizzled smem, double-buffered cp.async.
// ---------------------------------------------------------------------------
static constexpr int STAGE_BYTES = 128 * 128;
static constexpr int A0_OFF = 0;
static constexpr int A1_OFF = STAGE_BYTES;
static constexpr int B0_OFF = 2 * STAGE_BYTES;
static constexpr int B1_OFF = 3 * STAGE_BYTES;
static constexpr int SMEM_BYTES = 4 * STAGE_BYTES + 128;

DINL void load_chunk(uint32_t a_s, uint32_t b_s, int tid,
                     const __half* Abase, const __half* Bbase, int kc) {
    const __half* ap = Abase + kc * KCHUNK;
    const __half* bp = Bbase + kc * KCHUNK;
#pragma unroll
    for (int i = 0; i < 4; i++) {
        int idx = tid + i * 256;
        int row = idx >> 3, ch = idx & 7;
        uint32_t off = (uint32_t)(row * 128 + ch * 16);
        cp_async16(a_s + sw128(off), ap + (size_t)row * KTOT + ch * 8);
    }
#pragma unroll
    for (int i = 0; i < 4; i++) {
        int idx = tid + i * 256;
        int row = idx >> 3, ch = idx & 7;
        uint32_t off = (uint32_t)(row * 128 + ch * 16);
        cp_async16(b_s + sw128(off), bp + (size_t)row * KTOT + ch * 8);
    }
}

__global__ void __launch_bounds__(256, 2) mex_gemm(const __half* __restrict__ Ag,
                                                   const __half* __restrict__ Bg,
                                                   float* __restrict__ out) {
    extern __shared__ __align__(128) char smem_raw[];
    char* smem_al = (char*)(((uintptr_t)smem_raw + 127) & ~(uintptr_t)127);
    const uint32_t sb = smem_u32(smem_al);

    const int tid = threadIdx.x;
    const int l   = tid & 31;
    const int wid = tid >> 5;
    const int wm  = wid >> 2;       // 0..1 -> M offset wm*64
    const int wn  = wid & 3;        // 0..3 -> N offset wn*32

    const int n0 = blockIdx.x * NTILE;     // 0 or 128
    const int m0 = blockIdx.y * MTILE;
    const __half* Abase = Ag + (size_t)m0 * KTOT;
    const __half* Bbase = Bg + (size_t)n0 * KTOT;

    float acc[4][4][4];
#pragma unroll
    for (int a = 0; a < 4; a++)
#pragma unroll
        for (int b = 0; b < 4; b++)
#pragma unroll
            for (int e = 0; e < 4; e++) acc[a][b][e] = 0.0f;

    const uint32_t lrow = (uint32_t)(l & 15);
    const uint32_t lcol = (uint32_t)((l >> 4) * 16);

    load_chunk(sb + A0_OFF, sb + B0_OFF, tid, Abase, Bbase, 0);
    cp_commit();

    for (int kc = 0; kc < NCHUNK; kc++) {
        const int s = kc & 1;
        if (kc + 1 < NCHUNK) {
            load_chunk(sb + (s ? A0_OFF : A1_OFF), sb + (s ? B0_OFF : B1_OFF),
                       tid, Abase, Bbase, kc + 1);
            cp_commit();
            cp_wait<1>();
        } else {
            cp_wait<0>();
        }
        __syncthreads();

        const uint32_t a_s = sb + (s ? A1_OFF : A0_OFF);
        const uint32_t b_s = sb + (s ? B1_OFF : B0_OFF);
#pragma unroll
        for (int ks = 0; ks < 4; ks++) {
            uint32_t af[4][4], bf[2][4];
#pragma unroll
            for (int mt = 0; mt < 4; mt++) {
                uint32_t off = (uint32_t)((wm * 64 + mt * 16 + lrow) * 128 +
                                          ks * 32 + lcol);
                ldm_x4(a_s + sw128(off), af[mt][0], af[mt][1], af[mt][2], af[mt][3]);
            }
#pragma unroll
            for (int bt = 0; bt < 2; bt++) {
                uint32_t off = (uint32_t)((wn * 32 + bt * 16 + lrow) * 128 +
                                          ks * 32 + lcol);
                ldm_x4(b_s + sw128(off), bf[bt][0], bf[bt][1], bf[bt][2], bf[bt][3]);
            }
#pragma unroll
            for (int mt = 0; mt < 4; mt++)
#pragma unroll
                for (int nt = 0; nt < 4; nt++)
                    mma16816(acc[mt][nt], af[mt],
                             bf[nt >> 1][nt & 1], bf[nt >> 1][(nt & 1) + 2]);
        }
        __syncthreads();
    }

    // ---- epilogue: per 32-instance group, smem transpose -> log -> coalesced
    float* fs = (float*)smem_al;                 // 128 x 33 floats
    const int bglob = m0 >> 10;
    const int mrem  = m0 & 1023;
#pragma unroll 1
    for (int g = 0; g < 4; g++) {
        __syncthreads();
        if (wn == g) {
#pragma unroll
            for (int mt = 0; mt < 4; mt++)
#pragma unroll
                for (int nt = 0; nt < 4; nt++)
#pragma unroll
                    for (int e = 0; e < 4; e++) {
                        int row = (l >> 2) + (e >> 1) * 8;
                        int col = (l & 3) * 2 + (e & 1);
                        int ml = wm * 64 + mt * 16 + row;
                        int nl = nt * 8 + col;
                        fs[ml * 33 + nl] = __logf(acc[mt][nt][e]) - LOG_K;
                    }
        }
        __syncthreads();
        const int i_loc = tid >> 3;              // 0..31
        const int mc    = (tid & 7) * 16;        // 0..112
        const int i_glb = n0 + g * 32 + i_loc;
        float* ob = out + ((size_t)bglob << 18) + ((size_t)i_glb << 10) + mrem + mc;
#pragma unroll
        for (int j = 0; j < 4; j++) {
            float4 v;
            v.x = fs[(mc + j * 4 + 0) * 33 + i_loc];
            v.y = fs[(mc + j * 4 + 1) * 33 + i_loc];
            v.z = fs[(mc + j * 4 + 2) * 33 + i_loc];
            v.w = fs[(mc + j * 4 + 3) * 33 + i_loc];
            *reinterpret_cast<float4*>(ob + j * 4) = v;
        }
    }
}

// ---------------------------------------------------------------------------
extern "C" void kernel_launch(void* const* d_in, const int* in_sizes, int n_in,
                              void* d_out, int out_size) {
    const float* x    = (const float*)d_in[0];
    const float* offs = (const float*)d_in[1];
    if (n_in >= 2 && in_sizes[0] == NI * KTOT) {  // defensive: swap if order flipped
        const float* t = x; x = offs; offs = t;
    }
    float* out = (float*)d_out;

    __half *Ap = nullptr, *Bp = nullptr;
    cudaGetSymbolAddress((void**)&Ap, g_A);
    cudaGetSymbolAddress((void**)&Bp, g_B);
    cudaFuncSetAttribute(mex_pass1, cudaFuncAttributeMaxDynamicSharedMemorySize,
                         SLAB_BYTES);
    cudaFuncSetAttribute(mex_gemm, cudaFuncAttributeMaxDynamicSharedMemorySize,
                         SMEM_BYTES);

    // pass1 first so ncu (-s 5 -c 1) profiles the NEW pass1
    mex_pass1<<<64 * 32, 256, SLAB_BYTES>>>(x, Ap);
    mex_pass0<<<(NI * KTOT + 255) / 256, 256>>>(offs, Bp);
    dim3 grid(2, NPIX / MTILE);
    mex_gemm<<<grid, 256, SMEM_BYTES>>>(Ap, Bp, out);
}

// round 9
// speedup vs baseline: 1.7604x; 1.1640x over previous
#include <cuda_runtime.h>
#include <cuda_fp16.h>
#include <cstdint>
#include <cstddef>

// ============================================================================
// Mex forward, fused: y[n,i] = log( sum_k exp(P[n,k]) * exp(O[i,k]) ) - ln(576)
// K permuted: k' = f*64 + c (f = fh*3+fw), applied to both operands.
// pass0: exp(offsets) -> fp16 B (gmem, 288 KB, L2-resident)
// fused: per-CTA x slab (5 ih rows, c-fastest, fp16 exp) -> per-chunk A build
//        (one LDS.128 per 16B, chunk == fixed f) -> mma.sync GEMM -> log epi.
// CTA tile 64M x 128N, 256 thr, smem 96 KB -> 2 CTA/SM (fill overlaps MMA).
// No A matrix in gmem (saves ~150 MB traffic + the whole pass1 kernel).
// ============================================================================

#define DINL __device__ __forceinline__

static constexpr int NI   = 256;
static constexpr int KTOT = 576;
static constexpr int NCHUNK = 9;
static constexpr float LOG_K = 6.3561076606958915f;  // ln(576)

static constexpr int SLAB_P = 72;                      // halves per (ihl,iw') row
static constexpr int SLAB_BYTES_RAW = 5 * 65 * SLAB_P * 2;   // 46800
static constexpr int A_OFF   = 46848;                  // 128-aligned
static constexpr int A_STAGE = 64 * 128;               // 8 KB
static constexpr int B_OFF   = A_OFF + 2 * A_STAGE;    // 63232
static constexpr int B_STAGE = 128 * 128;              // 16 KB
static constexpr int SMEM_BYTES = B_OFF + 2 * B_STAGE; // 96000

__device__ __half g_B[(size_t)NI * KTOT];              // exp(offsets), permuted K

// ---------------------------------------------------------------------------
DINL uint32_t smem_u32(const void* p) {
    uint32_t a;
    asm("{ .reg .u64 t; cvta.to.shared.u64 t, %1; cvt.u32.u64 %0, t; }"
        : "=r"(a) : "l"(p));
    return a;
}
DINL void cp_async16(uint32_t smem_addr, const void* gptr) {
    asm volatile("cp.async.cg.shared.global [%0], [%1], 16;"
                 :: "r"(smem_addr), "l"(gptr) : "memory");
}
DINL void cp_commit() { asm volatile("cp.async.commit_group;" ::: "memory"); }
template <int N> DINL void cp_wait() {
    asm volatile("cp.async.wait_group %0;" :: "n"(N) : "memory");
}
DINL void ldm_x4(uint32_t addr, uint32_t& r0, uint32_t& r1,
                 uint32_t& r2, uint32_t& r3) {
    asm volatile("ldmatrix.sync.aligned.m8n8.x4.shared.b16 {%0,%1,%2,%3}, [%4];"
                 : "=r"(r0), "=r"(r1), "=r"(r2), "=r"(r3) : "r"(addr));
}
DINL void mma16816(float* c, const uint32_t* a, uint32_t b0, uint32_t b1) {
    asm volatile(
        "mma.sync.aligned.m16n8k16.row.col.f32.f16.f16.f32 "
        "{%0,%1,%2,%3}, {%4,%5,%6,%7}, {%8,%9}, {%0,%1,%2,%3};"
        : "+f"(c[0]), "+f"(c[1]), "+f"(c[2]), "+f"(c[3])
        : "r"(a[0]), "r"(a[1]), "r"(a[2]), "r"(a[3]), "r"(b0), "r"(b1));
}
DINL uint32_t sw128(uint32_t off) { return off ^ ((off >> 3) & 0x70); }

// ---------------------------------------------------------------------------
// pass0: B'[i, f*64+c] = fp16(exp(offsets[i, c*9+f]))
// ---------------------------------------------------------------------------
__global__ void mex_pass0(const float* __restrict__ offs, __half* __restrict__ Bm) {
    int j = blockIdx.x * blockDim.x + threadIdx.x;
    if (j < NI * KTOT) {
        int i = j / KTOT;
        int r = j - i * KTOT;
        int f = r >> 6;
        int c = r & 63;
        Bm[j] = __float2half_rn(__expf(offs[i * KTOT + c * 9 + f]));
    }
}

// ---------------------------------------------------------------------------
// fused kernel.  grid = (2, 1024): x = N-split (n0 = 0/128),
// y = b*16 + p (p = oh-pair, oh = 2p, 2p+1).  256 threads, 8 warps.
// M rows: m = ohl*32 + ow (64).  Slab xs[ihl 0..4][iw' 0..64][c pad 72].
// ---------------------------------------------------------------------------
__global__ void __launch_bounds__(256, 2) mex_fused(const float* __restrict__ x,
                                                    const __half* __restrict__ Bg,
                                                    float* __restrict__ out) {
    extern __shared__ __align__(128) char sm[];
    __half* xs = reinterpret_cast<__half*>(sm);
    const uint32_t sb = smem_u32(sm);

    const int tid = threadIdx.x;
    const int l   = tid & 31;
    const int wid = tid >> 5;

    const int n0 = blockIdx.x << 7;          // 0 or 128
    const int bo = blockIdx.y;
    const int b  = bo >> 4;
    const int p  = bo & 15;                  // oh pair
    const float* xb = x + ((size_t)b << 18);

    // ---- slab fill: warp wid owns c-octet c0 = wid*8; register transpose ----
    {
        const int c0 = wid << 3;
#pragma unroll
        for (int ihl = 0; ihl < 5; ihl++) {
            const int ih = 4 * p - 1 + ihl;          // -1..63
#pragma unroll
            for (int h = 0; h < 2; h++) {
                const int w = (h << 5) + l;          // 0..63
                __align__(16) __half tmp[8];
                if (ih >= 0) {
                    const float* ptr = xb + ((size_t)c0 << 12) + (ih << 6) + w;
#pragma unroll
                    for (int j = 0; j < 8; j++)
                        tmp[j] = __float2half_rn(__expf(ptr[(size_t)j << 12]));
                } else {
#pragma unroll
                    for (int j = 0; j < 8; j++) tmp[j] = __ushort_as_half(0x3C00);
                }
                *reinterpret_cast<uint4*>(&xs[(ihl * 65 + w + 1) * SLAB_P + c0]) =
                    *reinterpret_cast<const uint4*>(tmp);
            }
        }
        // left pad iw'=0 (exp(0)=1): 5 rows x 64 c = 160 half2 (tid < 160 < 256!)
        if (tid < 160) {
            int ihl = tid >> 5;
            int c2  = (tid & 31) << 1;
            *reinterpret_cast<__half2*>(&xs[(ihl * 65) * SLAB_P + c2]) =
                __halves2half2(__ushort_as_half(0x3C00), __ushort_as_half(0x3C00));
        }
    }
    __syncthreads();

    // ---- helpers (lambdas keep smem pointers in scope) ----
    auto build_A = [&](int stage, int kc) {
        const int fh = (kc * 11) >> 5;       // kc/3
        const int fw = kc - 3 * fh;
        char* astage = sm + A_OFF + stage * A_STAGE;
#pragma unroll
        for (int it = 0; it < 2; it++) {
            int idx = it * 256 + tid;        // 0..511
            int r   = idx >> 3;              // 0..63
            int cq  = idx & 7;
            int ohl = r >> 5;
            int ow  = r & 31;
            uint4 v = *reinterpret_cast<const uint4*>(
                &xs[((2 * ohl + fh) * 65 + 2 * ow + fw) * SLAB_P + (cq << 3)]);
            *reinterpret_cast<uint4*>(astage + sw128((uint32_t)(r * 128 + cq * 16))) = v;
        }
    };
    auto load_B = [&](int stage, int kc) {
        const uint32_t b_s = sb + B_OFF + stage * B_STAGE;
        const __half* bp = Bg + (size_t)n0 * KTOT + kc * 64;
#pragma unroll
        for (int i = 0; i < 4; i++) {
            int idx = tid + i * 256;         // 0..1023
            int row = idx >> 3, ch = idx & 7;
            uint32_t off = (uint32_t)(row * 128 + ch * 16);
            cp_async16(b_s + sw128(off), bp + (size_t)row * KTOT + ch * 8);
        }
        cp_commit();
    };

    // ---- prologue ----
    build_A(0, 0);
    load_B(0, 0);

    const int wm = wid & 1;                  // M band wm*32
    const int wn = wid >> 1;                 // N band wn*32
    float acc[2][4][4];
#pragma unroll
    for (int a = 0; a < 2; a++)
#pragma unroll
        for (int n = 0; n < 4; n++)
#pragma unroll
            for (int e = 0; e < 4; e++) acc[a][n][e] = 0.0f;

    const uint32_t lrow = (uint32_t)(l & 15);
    const uint32_t lcol = (uint32_t)((l >> 4) * 16);

    // ---- mainloop: single barrier per chunk ----
    for (int kc = 0; kc < NCHUNK; kc++) {
        const int s = kc & 1;
        if (kc + 1 < NCHUNK) {
            load_B(s ^ 1, kc + 1);           // into opposite stage (safe: last
            cp_wait<1>();                    //  read finished before prev barrier)
        } else {
            cp_wait<0>();
        }
        __syncthreads();                     // A build(kc) + B(kc) visible

        const uint32_t a_s = sb + A_OFF + s * A_STAGE;
        const uint32_t b_s = sb + B_OFF + s * B_STAGE;
#pragma unroll
        for (int ks = 0; ks < 4; ks++) {
            uint32_t af[2][4], bf[2][4];
#pragma unroll
            for (int mt = 0; mt < 2; mt++) {
                uint32_t off = (uint32_t)((wm * 32 + mt * 16 + lrow) * 128 +
                                          ks * 32 + lcol);
                ldm_x4(a_s + sw128(off), af[mt][0], af[mt][1], af[mt][2], af[mt][3]);
            }
#pragma unroll
            for (int bt = 0; bt < 2; bt++) {
                uint32_t off = (uint32_t)((wn * 32 + bt * 16 + lrow) * 128 +
                                          ks * 32 + lcol);
                ldm_x4(b_s + sw128(off), bf[bt][0], bf[bt][1], bf[bt][2], bf[bt][3]);
            }
#pragma unroll
            for (int mt = 0; mt < 2; mt++)
#pragma unroll
                for (int nt = 0; nt < 4; nt++)
                    mma16816(acc[mt][nt], af[mt],
                             bf[nt >> 1][nt & 1], bf[nt >> 1][(nt & 1) + 2]);
        }

        if (kc + 1 < NCHUNK)
            build_A(s ^ 1, kc + 1);          // overlaps other warps' MMA tails
    }

    // ---- epilogue: 4 groups of 32 instances; transpose in smem (reuse slab) ----
    float* fs = reinterpret_cast<float*>(sm);        // [64][33] floats = 8448 B
#pragma unroll 1
    for (int g = 0; g < 4; g++) {
        __syncthreads();
        if (wn == g) {
#pragma unroll
            for (int mt = 0; mt < 2; mt++)
#pragma unroll
                for (int nt = 0; nt < 4; nt++)
#pragma unroll
                    for (int e = 0; e < 4; e++) {
                        int row = (l >> 2) + ((e >> 1) << 3);
                        int col = ((l & 3) << 1) + (e & 1);
                        int ml  = wm * 32 + mt * 16 + row;   // 0..63
                        int nl  = (nt << 3) + col;           // 0..31
                        fs[ml * 33 + nl] = __logf(acc[mt][nt][e]) - LOG_K;
                    }
        }
        __syncthreads();
        const int i_loc = tid >> 3;                  // 0..31
        const int mc    = (tid & 7) << 3;            // 0..56 (thread owns m mc..mc+7)
        float* ob = out + ((size_t)b << 18)
                        + (((size_t)(n0 + g * 32 + i_loc)) << 10) + p * 64 + mc;
#pragma unroll
        for (int j = 0; j < 2; j++) {
            float4 v;
            v.x = fs[(mc + j * 4 + 0) * 33 + i_loc];
            v.y = fs[(mc + j * 4 + 1) * 33 + i_loc];
            v.z = fs[(mc + j * 4 + 2) * 33 + i_loc];
            v.w = fs[(mc + j * 4 + 3) * 33 + i_loc];
            *reinterpret_cast<float4*>(ob + j * 4) = v;
        }
    }
}

// ---------------------------------------------------------------------------
extern "C" void kernel_launch(void* const* d_in, const int* in_sizes, int n_in,
                              void* d_out, int out_size) {
    const float* x    = (const float*)d_in[0];
    const float* offs = (const float*)d_in[1];
    if (n_in >= 2 && in_sizes[0] == NI * KTOT) {  // defensive: swap if order flipped
        const float* t = x; x = offs; offs = t;
    }
    float* out = (float*)d_out;

    __half* Bp = nullptr;
    cudaGetSymbolAddress((void**)&Bp, g_B);
    cudaFuncSetAttribute(mex_fused, cudaFuncAttributeMaxDynamicSharedMemorySize,
                         SMEM_BYTES);

    mex_pass0<<<(NI * KTOT + 255) / 256, 256>>>(offs, Bp);
    dim3 grid(2, 64 * 16);
    mex_fused<<<grid, 256, SMEM_BYTES>>>(x, Bp, out);
}